// round 7
// baseline (speedup 1.0000x reference)
#include <cuda_runtime.h>
#include <math.h>

#define S_LEN 4096
#define HID   2048
#define HQ    32
#define HKV   4
#define DH    128
#define QDIM  (HQ*DH)    // 4096
#define KVDIM (HKV*DH)   // 512

// Scratch (static __device__ arrays: allocation-free per harness rules)
__device__ float g_Q[S_LEN * QDIM];   // 64 MB
__device__ float g_K[S_LEN * KVDIM];  //  8 MB
__device__ float g_V[S_LEN * KVDIM];  //  8 MB
__device__ float g_A[S_LEN * QDIM];   // 64 MB  (attention output, pre-O-proj)

// ---------------------------------------------------------------------------
// SGEMM: C[M,N] = A[M,K] * B[K,N], all row-major. BM=BN=128, BK=16,
// 256 threads, 8x8 register microtile, double-buffered shared memory.
// ---------------------------------------------------------------------------
__global__ __launch_bounds__(256, 2)
void sgemm_kernel(const float* __restrict__ A, const float* __restrict__ B,
                  float* __restrict__ C, int M, int N, int Kd)
{
    __shared__ float As[2][16][128];
    __shared__ float Bs[2][16][128];

    const int tid = threadIdx.x;
    const int tx = tid & 15;          // N direction
    const int ty = tid >> 4;          // M direction
    const int bx = blockIdx.x, by = blockIdx.y;

    const float* Ab = A + (size_t)by * 128 * Kd;
    const float* Bb = B + (size_t)bx * 128;

    // per-thread load coordinates (2 chunks of 256 threads each)
    const int ar0 = tid >> 2,         ac0 = tid & 3;        // A chunk 0
    const int ar1 = (tid + 256) >> 2, ac1 = tid & 3;        // A chunk 1
    const int br0 = tid >> 5,         bc0 = tid & 31;       // B chunk 0
    const int br1 = (tid + 256) >> 5, bc1 = tid & 31;       // B chunk 1

    float4 pa0, pa1, pb0, pb1;

    // prefetch k0 = 0
    pa0 = *(const float4*)&Ab[(size_t)ar0 * Kd + ac0 * 4];
    pa1 = *(const float4*)&Ab[(size_t)ar1 * Kd + ac1 * 4];
    pb0 = *(const float4*)&Bb[(size_t)br0 * N + bc0 * 4];
    pb1 = *(const float4*)&Bb[(size_t)br1 * N + bc1 * 4];

    float acc[8][8];
#pragma unroll
    for (int i = 0; i < 8; i++)
#pragma unroll
        for (int j = 0; j < 8; j++) acc[i][j] = 0.f;

    // store tile 0 into buffer 0
    As[0][ac0*4+0][ar0] = pa0.x; As[0][ac0*4+1][ar0] = pa0.y;
    As[0][ac0*4+2][ar0] = pa0.z; As[0][ac0*4+3][ar0] = pa0.w;
    As[0][ac1*4+0][ar1] = pa1.x; As[0][ac1*4+1][ar1] = pa1.y;
    As[0][ac1*4+2][ar1] = pa1.z; As[0][ac1*4+3][ar1] = pa1.w;
    *(float4*)&Bs[0][br0][bc0*4] = pb0;
    *(float4*)&Bs[0][br1][bc1*4] = pb1;
    __syncthreads();

    int buf = 0;
    for (int k0 = 16; k0 < Kd; k0 += 16) {
        // prefetch next slab (global loads issue before the FFMA block)
        pa0 = *(const float4*)&Ab[(size_t)ar0 * Kd + k0 + ac0 * 4];
        pa1 = *(const float4*)&Ab[(size_t)ar1 * Kd + k0 + ac1 * 4];
        pb0 = *(const float4*)&Bb[(size_t)(k0 + br0) * N + bc0 * 4];
        pb1 = *(const float4*)&Bb[(size_t)(k0 + br1) * N + bc1 * 4];

        // compute on current buffer
#pragma unroll
        for (int k = 0; k < 16; k++) {
            float ra[8], rb[8];
#pragma unroll
            for (int i = 0; i < 8; i++) ra[i] = As[buf][k][ty*8 + i];
#pragma unroll
            for (int j = 0; j < 8; j++) rb[j] = Bs[buf][k][tx*8 + j];
#pragma unroll
            for (int i = 0; i < 8; i++)
#pragma unroll
                for (int j = 0; j < 8; j++) acc[i][j] += ra[i] * rb[j];
        }

        // store prefetched slab into the other buffer
        int nb = buf ^ 1;
        As[nb][ac0*4+0][ar0] = pa0.x; As[nb][ac0*4+1][ar0] = pa0.y;
        As[nb][ac0*4+2][ar0] = pa0.z; As[nb][ac0*4+3][ar0] = pa0.w;
        As[nb][ac1*4+0][ar1] = pa1.x; As[nb][ac1*4+1][ar1] = pa1.y;
        As[nb][ac1*4+2][ar1] = pa1.z; As[nb][ac1*4+3][ar1] = pa1.w;
        *(float4*)&Bs[nb][br0][bc0*4] = pb0;
        *(float4*)&Bs[nb][br1][bc1*4] = pb1;
        __syncthreads();
        buf = nb;
    }

    // last tile
#pragma unroll
    for (int k = 0; k < 16; k++) {
        float ra[8], rb[8];
#pragma unroll
        for (int i = 0; i < 8; i++) ra[i] = As[buf][k][ty*8 + i];
#pragma unroll
        for (int j = 0; j < 8; j++) rb[j] = Bs[buf][k][tx*8 + j];
#pragma unroll
        for (int i = 0; i < 8; i++)
#pragma unroll
            for (int j = 0; j < 8; j++) acc[i][j] += ra[i] * rb[j];
    }

#pragma unroll
    for (int i = 0; i < 8; i++) {
        int row = by*128 + ty*8 + i;
#pragma unroll
        for (int j4 = 0; j4 < 2; j4++) {
            float4 v = make_float4(acc[i][j4*4+0], acc[i][j4*4+1],
                                   acc[i][j4*4+2], acc[i][j4*4+3]);
            *(float4*)&C[(size_t)row * N + bx*128 + tx*8 + j4*4] = v;
        }
    }
}

// ---------------------------------------------------------------------------
// RoPE (rotate-half), in place. X: [S, nheads, 128]. One thread per (s,h,d<64).
// ---------------------------------------------------------------------------
__global__ void rope_kernel(float* __restrict__ X, int nheads,
                            const int* __restrict__ pos)
{
    int idx = blockIdx.x * blockDim.x + threadIdx.x;
    int total = S_LEN * nheads * 64;
    if (idx >= total) return;
    int d    = idx & 63;
    int rest = idx >> 6;
    int hh   = rest % nheads;
    int s    = rest / nheads;

    float inv_freq = (float)exp(-9.210340371976184 * (double)d / 64.0); // ln(1e4)
    float angle = (float)pos[s] * inv_freq;
    float sn, cs;
    sincosf(angle, &sn, &cs);

    size_t base = ((size_t)s * nheads + hh) * DH;
    float x1 = X[base + d];
    float x2 = X[base + d + 64];
    X[base + d]      = x1 * cs - x2 * sn;
    X[base + d + 64] = x2 * cs + x1 * sn;
}

// ---------------------------------------------------------------------------
// Flash attention, fp32, causal, GQA (8 Q-heads per KV-head).
// Block = (head, 64-query tile), 256 threads. 4-lane group per query row.
//   scores: lane g owns keys {g+4j : j<8}  (interleaved -> conflict-free Ks)
//   output: lane g owns dims  [g*32, g*32+32)  (contiguous -> LDS.128 on Vs,
//           per-lane permuted j4 order -> no bank conflict)
// K/V double-buffered: one barrier per key-tile, next tile's LDG issued
// before the compute phase. LPT q-tile order (heavy causal tiles first).
// ---------------------------------------------------------------------------
#define FL_SMEM ((64*132 + 2*32*132 + 2*32*128) * 4)   // 100352 B

__global__ __launch_bounds__(256)
void flash_kernel(const float* __restrict__ Q, const float* __restrict__ Kb,
                  const float* __restrict__ Vb, float* __restrict__ O)
{
    extern __shared__ float sm[];
    float* Qs = sm;                     // [64][132]
    float* Ks0 = Qs + 64 * 132;         // [2][32][132]
    float* Vs0 = Ks0 + 2 * 32 * 132;    // [2][32][128]

    const int h   = blockIdx.x;
    const int q0  = (gridDim.y - 1 - blockIdx.y) * 64;   // LPT: heavy tiles first
    const int kvh = h >> 3;
    const int tid = threadIdx.x;
    const int qi  = tid >> 2;       // 0..63
    const int g   = tid & 3;
    const int lane = tid & 31;
    const int base = lane & ~3;

    // per-thread K/V tile coordinates (4 chunks of 256 threads)
    const int krow[4] = { (tid)>>5, (tid+256)>>5, (tid+512)>>5, (tid+768)>>5 };
    const int kc4 = tid & 31;

    // Load Q tile (64 x 128)
#pragma unroll
    for (int it = 0; it < 8; it++) {
        int lin = tid + it * 256;   // 0..2047
        int row = lin >> 5, c4 = lin & 31;
        *(float4*)&Qs[row*132 + c4*4] =
            *(const float4*)&Q[(size_t)(q0+row)*QDIM + h*DH + c4*4];
    }

    const float scale = 0.08838834764831845f;  // 1/sqrt(128)
    const int qg = q0 + qi;
    const int ntiles = (q0 + 64) / 32;         // causal: k up to q0+63; >= 2

    // prologue: K/V tile 0 -> buffer 0
#pragma unroll
    for (int it = 0; it < 4; it++) {
        size_t src = (size_t)krow[it]*KVDIM + kvh*DH + kc4*4;
        *(float4*)&Ks0[krow[it]*132 + kc4*4] = *(const float4*)&Kb[src];
        *(float4*)&Vs0[krow[it]*128 + kc4*4] = *(const float4*)&Vb[src];
    }
    __syncthreads();

    float m_run = -1e30f, l_run = 0.f;
    float o[32];                    // dims g*32 .. g*32+31
#pragma unroll
    for (int j = 0; j < 32; j++) o[j] = 0.f;

    int buf = 0;
    for (int kt = 0; kt < ntiles; kt++) {
        const int kbase = kt * 32;
        const float* Ks = Ks0 + buf * (32*132);
        const float* Vs = Vs0 + buf * (32*128);

        // issue next tile's global loads before compute
        float4 kreg[4], vreg[4];
        const bool more = (kt + 1 < ntiles);
        if (more) {
#pragma unroll
            for (int it = 0; it < 4; it++) {
                size_t src = (size_t)(kbase + 32 + krow[it])*KVDIM + kvh*DH + kc4*4;
                kreg[it] = *(const float4*)&Kb[src];
                vreg[it] = *(const float4*)&Vb[src];
            }
        }

        // scores for keys r = g + 4j
        float s[8];
#pragma unroll
        for (int j = 0; j < 8; j++) s[j] = 0.f;
#pragma unroll 4
        for (int d4 = 0; d4 < 32; d4++) {
            float4 q4 = *(const float4*)&Qs[qi*132 + d4*4];
#pragma unroll
            for (int j = 0; j < 8; j++) {
                float4 k4 = *(const float4*)&Ks[(g + 4*j)*132 + d4*4];
                s[j] += q4.x*k4.x + q4.y*k4.y + q4.z*k4.z + q4.w*k4.w;
            }
        }

        float mloc = -1e30f;
#pragma unroll
        for (int j = 0; j < 8; j++) {
            int kk = kbase + g + 4*j;
            s[j] = (kk <= qg) ? s[j] * scale : -1e30f;
            mloc = fmaxf(mloc, s[j]);
        }
        mloc = fmaxf(mloc, __shfl_xor_sync(0xffffffffu, mloc, 1));
        mloc = fmaxf(mloc, __shfl_xor_sync(0xffffffffu, mloc, 2));
        float m_new = fmaxf(m_run, mloc);
        float fac = expf(m_run - m_new);

        float psum = 0.f;
#pragma unroll
        for (int j = 0; j < 8; j++) { s[j] = expf(s[j] - m_new); psum += s[j]; }
        psum += __shfl_xor_sync(0xffffffffu, psum, 1);
        psum += __shfl_xor_sync(0xffffffffu, psum, 2);
        l_run = l_run * fac + psum;
        m_run = m_new;

#pragma unroll
        for (int j = 0; j < 32; j++) o[j] *= fac;

        // o[g*32+j] += p_k * V[k][g*32+j]; p gathered from the 4-lane group.
#pragma unroll
        for (int g2 = 0; g2 < 4; g2++) {
#pragma unroll
            for (int j2 = 0; j2 < 8; j2++) {
                float p = __shfl_sync(0xffffffffu, s[j2], base + g2);
                const float* vrow = &Vs[(g2 + 4*j2) * 128 + g * 32];
#pragma unroll
                for (int j4 = 0; j4 < 8; j4++) {
                    int jp = ((j4 + 2*g) & 7);
                    float4 v4 = *(const float4*)&vrow[jp*4];
                    o[jp*4+0] += p * v4.x;  o[jp*4+1] += p * v4.y;
                    o[jp*4+2] += p * v4.z;  o[jp*4+3] += p * v4.w;
                }
            }
        }

        // stage next tile into the other buffer; single barrier per iter
        if (more) {
            int nb = buf ^ 1;
            float* Kn = Ks0 + nb * (32*132);
            float* Vn = Vs0 + nb * (32*128);
#pragma unroll
            for (int it = 0; it < 4; it++) {
                *(float4*)&Kn[krow[it]*132 + kc4*4] = kreg[it];
                *(float4*)&Vn[krow[it]*128 + kc4*4] = vreg[it];
            }
            __syncthreads();
            buf = nb;
        }
    }

    float inv = 1.f / l_run;
    float* orow = &O[(size_t)qg*QDIM + h*DH + g*32];
#pragma unroll
    for (int j4 = 0; j4 < 8; j4++) {
        float4 v = make_float4(o[j4*4+0]*inv, o[j4*4+1]*inv,
                               o[j4*4+2]*inv, o[j4*4+3]*inv);
        *(float4*)&orow[j4*4] = v;
    }
}

// ---------------------------------------------------------------------------
extern "C" void kernel_launch(void* const* d_in, const int* in_sizes, int n_in,
                              void* d_out, int out_size)
{
    const float* X   = (const float*)d_in[0];   // [4096, 2048]
    const float* Wq  = (const float*)d_in[1];   // [2048, 4096]
    const float* Wk  = (const float*)d_in[2];   // [2048, 512]
    const float* Wv  = (const float*)d_in[3];   // [2048, 512]
    const float* Wo  = (const float*)d_in[4];   // [4096, 2048]
    const int*   pos = (const int*)d_in[5];     // [4096]
    // d_in[6] = attention_mask (causal bool) -- causality handled analytically
    float* out = (float*)d_out;                 // [4096, 2048]

    float *Qb, *Kb, *Vb, *Ab;
    cudaGetSymbolAddress((void**)&Qb, g_Q);
    cudaGetSymbolAddress((void**)&Kb, g_K);
    cudaGetSymbolAddress((void**)&Vb, g_V);
    cudaGetSymbolAddress((void**)&Ab, g_A);

    // Projections
    sgemm_kernel<<<dim3(QDIM/128,  S_LEN/128), 256>>>(X, Wq, Qb, S_LEN, QDIM,  HID);
    sgemm_kernel<<<dim3(KVDIM/128, S_LEN/128), 256>>>(X, Wk, Kb, S_LEN, KVDIM, HID);
    sgemm_kernel<<<dim3(KVDIM/128, S_LEN/128), 256>>>(X, Wv, Vb, S_LEN, KVDIM, HID);

    // RoPE on Q and K
    rope_kernel<<<(S_LEN*HQ*64  + 255)/256, 256>>>(Qb, HQ,  pos);
    rope_kernel<<<(S_LEN*HKV*64 + 255)/256, 256>>>(Kb, HKV, pos);

    // Causal GQA attention (double-buffered K/V, LPT block order)
    cudaFuncSetAttribute(flash_kernel,
                         cudaFuncAttributeMaxDynamicSharedMemorySize, FL_SMEM);
    flash_kernel<<<dim3(HQ, S_LEN/64), 256, FL_SMEM>>>(Qb, Kb, Vb, Ab);

    // Output projection (M=S_LEN, N=HID, Kd=QDIM)
    sgemm_kernel<<<dim3(HID/128, S_LEN/128), 256>>>(Ab, Wo, out, S_LEN, HID, QDIM);
}

// round 9
// speedup vs baseline: 9.8679x; 9.8679x over previous
#include <cuda_runtime.h>
#include <math.h>

#define S_LEN 4096
#define HID   2048
#define HQ    32
#define HKV   4
#define DH    128
#define QDIM  (HQ*DH)    // 4096
#define KVDIM (HKV*DH)   // 512

// Scratch (static __device__ arrays: allocation-free per harness rules)
__device__ float g_Q[S_LEN * QDIM];   // 64 MB
__device__ float g_K[S_LEN * KVDIM];  //  8 MB
__device__ float g_V[S_LEN * KVDIM];  //  8 MB
__device__ float g_A[S_LEN * QDIM];   // 64 MB  (attention output, pre-O-proj)

// ---------------------------------------------------------------------------
// SGEMM: C[M,N] = A[M,K] * B[K,N], all row-major. BM=BN=128, BK=16,
// 256 threads, 8x8 register microtile, double-buffered shared memory.
// ---------------------------------------------------------------------------
__global__ __launch_bounds__(256, 2)
void sgemm_kernel(const float* __restrict__ A, const float* __restrict__ B,
                  float* __restrict__ C, int M, int N, int Kd)
{
    __shared__ float As[2][16][128];
    __shared__ float Bs[2][16][128];

    const int tid = threadIdx.x;
    const int tx = tid & 15;          // N direction
    const int ty = tid >> 4;          // M direction
    const int bx = blockIdx.x, by = blockIdx.y;

    const float* Ab = A + (size_t)by * 128 * Kd;
    const float* Bb = B + (size_t)bx * 128;

    // per-thread load coordinates (2 chunks of 256 threads each)
    const int ar0 = tid >> 2,         ac0 = tid & 3;        // A chunk 0
    const int ar1 = (tid + 256) >> 2, ac1 = tid & 3;        // A chunk 1
    const int br0 = tid >> 5,         bc0 = tid & 31;       // B chunk 0
    const int br1 = (tid + 256) >> 5, bc1 = tid & 31;       // B chunk 1

    float4 pa0, pa1, pb0, pb1;

    // prefetch k0 = 0
    pa0 = *(const float4*)&Ab[(size_t)ar0 * Kd + ac0 * 4];
    pa1 = *(const float4*)&Ab[(size_t)ar1 * Kd + ac1 * 4];
    pb0 = *(const float4*)&Bb[(size_t)br0 * N + bc0 * 4];
    pb1 = *(const float4*)&Bb[(size_t)br1 * N + bc1 * 4];

    float acc[8][8];
#pragma unroll
    for (int i = 0; i < 8; i++)
#pragma unroll
        for (int j = 0; j < 8; j++) acc[i][j] = 0.f;

    // store tile 0 into buffer 0
    As[0][ac0*4+0][ar0] = pa0.x; As[0][ac0*4+1][ar0] = pa0.y;
    As[0][ac0*4+2][ar0] = pa0.z; As[0][ac0*4+3][ar0] = pa0.w;
    As[0][ac1*4+0][ar1] = pa1.x; As[0][ac1*4+1][ar1] = pa1.y;
    As[0][ac1*4+2][ar1] = pa1.z; As[0][ac1*4+3][ar1] = pa1.w;
    *(float4*)&Bs[0][br0][bc0*4] = pb0;
    *(float4*)&Bs[0][br1][bc1*4] = pb1;
    __syncthreads();

    int buf = 0;
    for (int k0 = 16; k0 < Kd; k0 += 16) {
        // prefetch next slab (global loads issue before the FFMA block)
        pa0 = *(const float4*)&Ab[(size_t)ar0 * Kd + k0 + ac0 * 4];
        pa1 = *(const float4*)&Ab[(size_t)ar1 * Kd + k0 + ac1 * 4];
        pb0 = *(const float4*)&Bb[(size_t)(k0 + br0) * N + bc0 * 4];
        pb1 = *(const float4*)&Bb[(size_t)(k0 + br1) * N + bc1 * 4];

        // compute on current buffer
#pragma unroll
        for (int k = 0; k < 16; k++) {
            float ra[8], rb[8];
#pragma unroll
            for (int i = 0; i < 8; i++) ra[i] = As[buf][k][ty*8 + i];
#pragma unroll
            for (int j = 0; j < 8; j++) rb[j] = Bs[buf][k][tx*8 + j];
#pragma unroll
            for (int i = 0; i < 8; i++)
#pragma unroll
                for (int j = 0; j < 8; j++) acc[i][j] += ra[i] * rb[j];
        }

        // store prefetched slab into the other buffer
        int nb = buf ^ 1;
        As[nb][ac0*4+0][ar0] = pa0.x; As[nb][ac0*4+1][ar0] = pa0.y;
        As[nb][ac0*4+2][ar0] = pa0.z; As[nb][ac0*4+3][ar0] = pa0.w;
        As[nb][ac1*4+0][ar1] = pa1.x; As[nb][ac1*4+1][ar1] = pa1.y;
        As[nb][ac1*4+2][ar1] = pa1.z; As[nb][ac1*4+3][ar1] = pa1.w;
        *(float4*)&Bs[nb][br0][bc0*4] = pb0;
        *(float4*)&Bs[nb][br1][bc1*4] = pb1;
        __syncthreads();
        buf = nb;
    }

    // last tile
#pragma unroll
    for (int k = 0; k < 16; k++) {
        float ra[8], rb[8];
#pragma unroll
        for (int i = 0; i < 8; i++) ra[i] = As[buf][k][ty*8 + i];
#pragma unroll
        for (int j = 0; j < 8; j++) rb[j] = Bs[buf][k][tx*8 + j];
#pragma unroll
        for (int i = 0; i < 8; i++)
#pragma unroll
            for (int j = 0; j < 8; j++) acc[i][j] += ra[i] * rb[j];
    }

#pragma unroll
    for (int i = 0; i < 8; i++) {
        int row = by*128 + ty*8 + i;
#pragma unroll
        for (int j4 = 0; j4 < 2; j4++) {
            float4 v = make_float4(acc[i][j4*4+0], acc[i][j4*4+1],
                                   acc[i][j4*4+2], acc[i][j4*4+3]);
            *(float4*)&C[(size_t)row * N + bx*128 + tx*8 + j4*4] = v;
        }
    }
}

// ---------------------------------------------------------------------------
// RoPE (rotate-half), in place. X: [S, nheads, 128]. One thread per (s,h,d<64).
// ---------------------------------------------------------------------------
__global__ void rope_kernel(float* __restrict__ X, int nheads,
                            const int* __restrict__ pos)
{
    int idx = blockIdx.x * blockDim.x + threadIdx.x;
    int total = S_LEN * nheads * 64;
    if (idx >= total) return;
    int d    = idx & 63;
    int rest = idx >> 6;
    int hh   = rest % nheads;
    int s    = rest / nheads;

    float inv_freq = (float)exp(-9.210340371976184 * (double)d / 64.0); // ln(1e4)
    float angle = (float)pos[s] * inv_freq;
    float sn, cs;
    sincosf(angle, &sn, &cs);

    size_t base = ((size_t)s * nheads + hh) * DH;
    float x1 = X[base + d];
    float x2 = X[base + d + 64];
    X[base + d]      = x1 * cs - x2 * sn;
    X[base + d + 64] = x2 * cs + x1 * sn;
}

// ---------------------------------------------------------------------------
// Flash attention, fp32, causal, GQA (8 Q-heads per KV-head).
// Block = (head, 64-query tile), 256 threads. 4-lane group per query row.
//   scores: lane g owns keys {g+4j : j<8}  (interleaved -> conflict-free Ks)
//   output: lane g owns dims  [g*32, g*32+32).
// PV loop: accumulator index is COMPILE-TIME (j4); only the Vs *address* is
// permuted per lane (conflict-free banks) -- keeps o[] in registers.
// Slot j4 holds dim-group jp=(j4+2g)&7; the final STG applies the mapping.
// K/V double-buffered (one barrier/tile); LPT q-tile order.
// ---------------------------------------------------------------------------
#define FL_SMEM ((64*132 + 2*32*132 + 2*32*128) * 4)   // 100352 B

__global__ __launch_bounds__(256)
void flash_kernel(const float* __restrict__ Q, const float* __restrict__ Kb,
                  const float* __restrict__ Vb, float* __restrict__ O)
{
    extern __shared__ float sm[];
    float* Qs = sm;                     // [64][132]
    float* Ks0 = Qs + 64 * 132;         // [2][32][132]
    float* Vs0 = Ks0 + 2 * 32 * 132;    // [2][32][128]

    const int h   = blockIdx.x;
    const int q0  = (gridDim.y - 1 - blockIdx.y) * 64;   // LPT: heavy tiles first
    const int kvh = h >> 3;
    const int tid = threadIdx.x;
    const int qi  = tid >> 2;       // 0..63
    const int g   = tid & 3;
    const int lane = tid & 31;
    const int base = lane & ~3;

    // per-thread K/V tile coordinates (4 chunks of 256 threads)
    const int krow[4] = { (tid)>>5, (tid+256)>>5, (tid+512)>>5, (tid+768)>>5 };
    const int kc4 = tid & 31;

    // Load Q tile (64 x 128)
#pragma unroll
    for (int it = 0; it < 8; it++) {
        int lin = tid + it * 256;   // 0..2047
        int row = lin >> 5, c4 = lin & 31;
        *(float4*)&Qs[row*132 + c4*4] =
            *(const float4*)&Q[(size_t)(q0+row)*QDIM + h*DH + c4*4];
    }

    const float scale = 0.08838834764831845f;  // 1/sqrt(128)
    const int qg = q0 + qi;
    const int ntiles = (q0 + 64) / 32;         // causal: k up to q0+63; >= 2

    // prologue: K/V tile 0 -> buffer 0
#pragma unroll
    for (int it = 0; it < 4; it++) {
        size_t src = (size_t)krow[it]*KVDIM + kvh*DH + kc4*4;
        *(float4*)&Ks0[krow[it]*132 + kc4*4] = *(const float4*)&Kb[src];
        *(float4*)&Vs0[krow[it]*128 + kc4*4] = *(const float4*)&Vb[src];
    }
    __syncthreads();

    float m_run = -1e30f, l_run = 0.f;
    float o[32];                    // slot j4*4+c  <->  output dim g*32 + ((j4+2g)&7)*4 + c
#pragma unroll
    for (int j = 0; j < 32; j++) o[j] = 0.f;

    int buf = 0;
    for (int kt = 0; kt < ntiles; kt++) {
        const int kbase = kt * 32;
        const float* Ks = Ks0 + buf * (32*132);
        const float* Vs = Vs0 + buf * (32*128);

        // issue next tile's global loads before compute
        float4 kreg[4], vreg[4];
        const bool more = (kt + 1 < ntiles);
        if (more) {
#pragma unroll
            for (int it = 0; it < 4; it++) {
                size_t src = (size_t)(kbase + 32 + krow[it])*KVDIM + kvh*DH + kc4*4;
                kreg[it] = *(const float4*)&Kb[src];
                vreg[it] = *(const float4*)&Vb[src];
            }
        }

        // scores for keys r = g + 4j
        float s[8];
#pragma unroll
        for (int j = 0; j < 8; j++) s[j] = 0.f;
#pragma unroll 4
        for (int d4 = 0; d4 < 32; d4++) {
            float4 q4 = *(const float4*)&Qs[qi*132 + d4*4];
#pragma unroll
            for (int j = 0; j < 8; j++) {
                float4 k4 = *(const float4*)&Ks[(g + 4*j)*132 + d4*4];
                s[j] += q4.x*k4.x + q4.y*k4.y + q4.z*k4.z + q4.w*k4.w;
            }
        }

        float mloc = -1e30f;
#pragma unroll
        for (int j = 0; j < 8; j++) {
            int kk = kbase + g + 4*j;
            s[j] = (kk <= qg) ? s[j] * scale : -1e30f;
            mloc = fmaxf(mloc, s[j]);
        }
        mloc = fmaxf(mloc, __shfl_xor_sync(0xffffffffu, mloc, 1));
        mloc = fmaxf(mloc, __shfl_xor_sync(0xffffffffu, mloc, 2));
        float m_new = fmaxf(m_run, mloc);
        float fac = expf(m_run - m_new);

        float psum = 0.f;
#pragma unroll
        for (int j = 0; j < 8; j++) { s[j] = expf(s[j] - m_new); psum += s[j]; }
        psum += __shfl_xor_sync(0xffffffffu, psum, 1);
        psum += __shfl_xor_sync(0xffffffffu, psum, 2);
        l_run = l_run * fac + psum;
        m_run = m_new;

#pragma unroll
        for (int j = 0; j < 32; j++) o[j] *= fac;

        // o[slot j4] += p_k * V[k][permuted dim]; accumulator index compile-time,
        // only the LDS address is lane-permuted (conflict-free banks).
        const float* vbase = Vs + g * 32;
#pragma unroll
        for (int g2 = 0; g2 < 4; g2++) {
#pragma unroll
            for (int j2 = 0; j2 < 8; j2++) {
                float p = __shfl_sync(0xffffffffu, s[j2], base + g2);
                const float* vrow = vbase + (g2 + 4*j2) * 128;
#pragma unroll
                for (int j4 = 0; j4 < 8; j4++) {
                    float4 v4 = *(const float4*)&vrow[((j4 + 2*g) & 7) * 4];
                    o[j4*4+0] += p * v4.x;  o[j4*4+1] += p * v4.y;
                    o[j4*4+2] += p * v4.z;  o[j4*4+3] += p * v4.w;
                }
            }
        }

        // stage next tile into the other buffer; single barrier per iter
        if (more) {
            int nb = buf ^ 1;
            float* Kn = Ks0 + nb * (32*132);
            float* Vn = Vs0 + nb * (32*128);
#pragma unroll
            for (int it = 0; it < 4; it++) {
                *(float4*)&Kn[krow[it]*132 + kc4*4] = kreg[it];
                *(float4*)&Vn[krow[it]*128 + kc4*4] = vreg[it];
            }
            __syncthreads();
            buf = nb;
        }
    }

    float inv = 1.f / l_run;
    float* orow = &O[(size_t)qg*QDIM + h*DH + g*32];
#pragma unroll
    for (int j4 = 0; j4 < 8; j4++) {
        int jp = (j4 + 2*g) & 7;               // slot j4 holds dim-group jp
        float4 v = make_float4(o[j4*4+0]*inv, o[j4*4+1]*inv,
                               o[j4*4+2]*inv, o[j4*4+3]*inv);
        *(float4*)&orow[jp*4] = v;
    }
}

// ---------------------------------------------------------------------------
extern "C" void kernel_launch(void* const* d_in, const int* in_sizes, int n_in,
                              void* d_out, int out_size)
{
    const float* X   = (const float*)d_in[0];   // [4096, 2048]
    const float* Wq  = (const float*)d_in[1];   // [2048, 4096]
    const float* Wk  = (const float*)d_in[2];   // [2048, 512]
    const float* Wv  = (const float*)d_in[3];   // [2048, 512]
    const float* Wo  = (const float*)d_in[4];   // [4096, 2048]
    const int*   pos = (const int*)d_in[5];     // [4096]
    // d_in[6] = attention_mask (causal bool) -- causality handled analytically
    float* out = (float*)d_out;                 // [4096, 2048]

    float *Qb, *Kb, *Vb, *Ab;
    cudaGetSymbolAddress((void**)&Qb, g_Q);
    cudaGetSymbolAddress((void**)&Kb, g_K);
    cudaGetSymbolAddress((void**)&Vb, g_V);
    cudaGetSymbolAddress((void**)&Ab, g_A);

    // Projections
    sgemm_kernel<<<dim3(QDIM/128,  S_LEN/128), 256>>>(X, Wq, Qb, S_LEN, QDIM,  HID);
    sgemm_kernel<<<dim3(KVDIM/128, S_LEN/128), 256>>>(X, Wk, Kb, S_LEN, KVDIM, HID);
    sgemm_kernel<<<dim3(KVDIM/128, S_LEN/128), 256>>>(X, Wv, Vb, S_LEN, KVDIM, HID);

    // RoPE on Q and K
    rope_kernel<<<(S_LEN*HQ*64  + 255)/256, 256>>>(Qb, HQ,  pos);
    rope_kernel<<<(S_LEN*HKV*64 + 255)/256, 256>>>(Kb, HKV, pos);

    // Causal GQA attention (double-buffered K/V, LPT block order)
    cudaFuncSetAttribute(flash_kernel,
                         cudaFuncAttributeMaxDynamicSharedMemorySize, FL_SMEM);
    flash_kernel<<<dim3(HQ, S_LEN/64), 256, FL_SMEM>>>(Qb, Kb, Vb, Ab);

    // Output projection (M=S_LEN, N=HID, Kd=QDIM)
    sgemm_kernel<<<dim3(HID/128, S_LEN/128), 256>>>(Ab, Wo, out, S_LEN, HID, QDIM);
}